// round 1
// baseline (speedup 1.0000x reference)
#include <cuda_runtime.h>

// Problem constants (fixed by the dataset)
#define B_   4
#define NQ_  16384
#define C_   256
#define NH_  8
#define NP_  4
#define H_   128
#define W_   128
#define HD_  32
#define M_   (B_ * NQ_)      // 65536 rows for query-side GEMMs
#define HW_  (H_ * W_)       // 16384 (== NQ_, so value GEMM also has M_ rows total)

// Scratch (allocation-free rule: __device__ globals)
__device__ float g_off    [(size_t)M_ * 64];        // [M, NH*NP*2]
__device__ float g_logits [(size_t)M_ * 32];        // [M, NH*NP]
__device__ float g_vproj  [(size_t)B_ * HW_ * C_];  // [B, HW, C]
__device__ float g_sampled[(size_t)M_ * C_];        // [M, C]

// ---------------------------------------------------------------------------
// C[M,N] = A[M,K] @ B[K,N] + bias[N]   (all row-major, fp32)
// Tile: 64x64x16, 256 threads, 4x4 per-thread micro-tile.
// Requires M % 64 == 0, K % 16 == 0, N % 4 == 0. N may be < 64 (guarded).
// ---------------------------------------------------------------------------
__global__ __launch_bounds__(256) void sgemm64(
    const float* __restrict__ A, const float* __restrict__ Bm,
    const float* __restrict__ bias, float* __restrict__ C,
    int M, int N, int K)
{
    constexpr int TM = 64, TN = 64, TK = 16;
    __shared__ float As[TK][TM + 4];   // +4 pad (keeps 16B alignment, breaks conflicts)
    __shared__ float Bs[TK][TN];

    const int tid = threadIdx.x;
    const int tx = tid & 15;          // 0..15 -> N micro index
    const int ty = tid >> 4;          // 0..15 -> M micro index
    const int bm = blockIdx.y * TM;
    const int bn = blockIdx.x * TN;

    // A loader: 64 rows x 16 cols as float4
    const int a_row = tid >> 2;          // 0..63
    const int a_col = (tid & 3) << 2;    // 0,4,8,12
    // B loader: 16 rows x 64 cols as float4
    const int b_row = tid >> 4;          // 0..15
    const int b_col = (tid & 15) << 2;   // 0..60

    float acc[4][4] = {};

    for (int k0 = 0; k0 < K; k0 += TK) {
        float4 av = *(const float4*)(A + (size_t)(bm + a_row) * K + k0 + a_col);
        As[a_col + 0][a_row] = av.x;
        As[a_col + 1][a_row] = av.y;
        As[a_col + 2][a_row] = av.z;
        As[a_col + 3][a_row] = av.w;

        float4 bv = make_float4(0.f, 0.f, 0.f, 0.f);
        if (bn + b_col < N)
            bv = *(const float4*)(Bm + (size_t)(k0 + b_row) * N + bn + b_col);
        *(float4*)&Bs[b_row][b_col] = bv;

        __syncthreads();

        #pragma unroll
        for (int k = 0; k < TK; k++) {
            float4 a4 = *(const float4*)&As[k][ty << 2];
            float4 b4 = *(const float4*)&Bs[k][tx << 2];
            float af[4] = {a4.x, a4.y, a4.z, a4.w};
            float bf[4] = {b4.x, b4.y, b4.z, b4.w};
            #pragma unroll
            for (int i = 0; i < 4; i++)
                #pragma unroll
                for (int j = 0; j < 4; j++)
                    acc[i][j] = fmaf(af[i], bf[j], acc[i][j]);
        }
        __syncthreads();
    }

    #pragma unroll
    for (int i = 0; i < 4; i++) {
        const int row = bm + (ty << 2) + i;
        #pragma unroll
        for (int j = 0; j < 4; j++) {
            const int col = bn + (tx << 2) + j;
            if (col < N)
                C[(size_t)row * N + col] = acc[i][j] + bias[col];
        }
    }
}

// ---------------------------------------------------------------------------
// Sampler: one warp per (query, head); lane = channel within HD=32.
// Reads g_off / g_logits / g_vproj, writes g_sampled.
// Each corner gather is one coalesced 128B (32 x fp32) segment.
// ---------------------------------------------------------------------------
__global__ __launch_bounds__(256) void sample_kernel(const float* __restrict__ ref)
{
    const int gw   = (blockIdx.x * 256 + threadIdx.x) >> 5;  // global warp id
    const int lane = threadIdx.x & 31;
    if (gw >= M_ * NH_) return;
    const int m = gw >> 3;   // query row (0..65535)
    const int h = gw & 7;    // head
    const int b = m / NQ_;

    const float rx = ref[2 * m + 0];
    const float ry = ref[2 * m + 1];

    // softmax over NP=4 points of this head
    const float* lg = g_logits + (size_t)m * 32 + h * 4;
    const float l0 = lg[0], l1 = lg[1], l2 = lg[2], l3 = lg[3];
    const float mx = fmaxf(fmaxf(l0, l1), fmaxf(l2, l3));
    const float e0 = __expf(l0 - mx), e1 = __expf(l1 - mx);
    const float e2 = __expf(l2 - mx), e3 = __expf(l3 - mx);
    const float inv = 1.f / (e0 + e1 + e2 + e3);
    const float w4[4] = {e0 * inv, e1 * inv, e2 * inv, e3 * inv};

    const float* off = g_off + (size_t)m * 64 + h * 8;        // [NP][2]
    const float* vb  = g_vproj + (size_t)b * HW_ * C_ + h * HD_ + lane;

    float acc = 0.f;
    #pragma unroll
    for (int p = 0; p < 4; p++) {
        const float lx = fminf(fmaxf(rx + off[2 * p + 0] * (0.1f / W_), 0.f), 1.f);
        const float ly = fminf(fmaxf(ry + off[2 * p + 1] * (0.1f / H_), 0.f), 1.f);
        const float ix = lx * (float)W_ - 0.5f;
        const float iy = ly * (float)H_ - 0.5f;
        const float x0f = floorf(ix), y0f = floorf(iy);
        const float wx = ix - x0f, wy = iy - y0f;
        const int x0 = (int)x0f, y0 = (int)y0f;

        const bool xi0 = (x0 >= 0) && (x0 < W_);
        const bool xi1 = (x0 + 1 < W_);   // x0+1 >= 0 always (x0 >= -1)
        const bool yi0 = (y0 >= 0) && (y0 < H_);
        const bool yi1 = (y0 + 1 < H_);

        float s = 0.f;
        if (yi0) {
            const float* r0 = vb + (size_t)(y0 * W_) * C_;
            if (xi0) s += (1.f - wx) * (1.f - wy) * r0[(size_t)x0 * C_];
            if (xi1) s +=        wx  * (1.f - wy) * r0[(size_t)(x0 + 1) * C_];
        }
        if (yi1) {
            const float* r1 = vb + (size_t)((y0 + 1) * W_) * C_;
            if (xi0) s += (1.f - wx) * wy * r1[(size_t)x0 * C_];
            if (xi1) s +=        wx  * wy * r1[(size_t)(x0 + 1) * C_];
        }
        acc = fmaf(w4[p], s, acc);
    }

    g_sampled[(size_t)m * C_ + h * HD_ + lane] = acc;
}

// ---------------------------------------------------------------------------
extern "C" void kernel_launch(void* const* d_in, const int* in_sizes, int n_in,
                              void* d_out, int out_size)
{
    const float* query  = (const float*)d_in[0];
    const float* refp   = (const float*)d_in[1];
    const float* value  = (const float*)d_in[2];
    const float* W_off  = (const float*)d_in[3];
    const float* b_off  = (const float*)d_in[4];
    const float* W_attn = (const float*)d_in[5];
    const float* b_attn = (const float*)d_in[6];
    const float* W_v    = (const float*)d_in[7];
    const float* b_v    = (const float*)d_in[8];
    const float* W_out  = (const float*)d_in[9];
    const float* b_out  = (const float*)d_in[10];
    float* out = (float*)d_out;

    float *p_off, *p_log, *p_vp, *p_s;
    cudaGetSymbolAddress((void**)&p_off, g_off);
    cudaGetSymbolAddress((void**)&p_log, g_logits);
    cudaGetSymbolAddress((void**)&p_vp,  g_vproj);
    cudaGetSymbolAddress((void**)&p_s,   g_sampled);

    dim3 blk(256);

    // 1) sampling-offset projection: [M,256] @ [256,64] + b
    sgemm64<<<dim3(1, M_ / 64), blk>>>(query, W_off, b_off, p_off, M_, 64, C_);
    // 2) attention-logit projection: [M,256] @ [256,32] + b
    sgemm64<<<dim3(1, M_ / 64), blk>>>(query, W_attn, b_attn, p_log, M_, 32, C_);
    // 3) value projection: [B*HW,256] @ [256,256] + b
    sgemm64<<<dim3(C_ / 64, M_ / 64), blk>>>(value, W_v, b_v, p_vp, M_, C_, C_);
    // 4) softmax + bilinear deformable sampling
    sample_kernel<<<(M_ * NH_ * 32) / 256, blk>>>(refp);
    // 5) output projection: [M,256] @ [256,256] + b -> d_out
    sgemm64<<<dim3(C_ / 64, M_ / 64), blk>>>(p_s, W_out, b_out, out, M_, C_, C_);
}

// round 2
// speedup vs baseline: 1.3137x; 1.3137x over previous
#include <cuda_runtime.h>

// Problem constants (fixed by the dataset)
#define B_   4
#define NQ_  16384
#define C_   256
#define NH_  8
#define NP_  4
#define H_   128
#define W_   128
#define HD_  32
#define M_   (B_ * NQ_)      // 65536 rows
#define HW_  (H_ * W_)       // 16384

// Scratch (__device__ globals: allocation-free rule)
__device__ float g_qp     [(size_t)M_ * 96];        // [M, 64 off | 32 logits]
__device__ float g_vproj  [(size_t)B_ * HW_ * C_];  // [B, HW, C]
__device__ float g_sampled[(size_t)M_ * C_];        // [M, C]
__device__ float g_Wqp    [256 * 96];               // packed W_off|W_attn
__device__ float g_bqp    [96];                     // packed b_off|b_attn

// ---------------------------------------------------------------------------
// Pack W_off (256x64) + W_attn (256x32) -> g_Wqp (256x96); biases likewise.
// ---------------------------------------------------------------------------
__global__ void pack_qp(const float* __restrict__ W_off, const float* __restrict__ b_off,
                        const float* __restrict__ W_attn, const float* __restrict__ b_attn)
{
    int idx = blockIdx.x * 256 + threadIdx.x;
    if (idx < 256 * 96) {
        int row = idx / 96, col = idx % 96;
        g_Wqp[idx] = (col < 64) ? W_off[row * 64 + col] : W_attn[row * 32 + (col - 64)];
    }
    if (idx < 96)
        g_bqp[idx] = (idx < 64) ? b_off[idx] : b_attn[idx - 64];
}

// ---------------------------------------------------------------------------
// C[M,N] = A[M,K] @ B[K,N] + bias[N]  (row-major fp32)
// 128x128x8 tile, 256 threads, 8x8 micro-tile, double-buffered smem.
// Requires M%128==0, K%8==0. NG=true allows N<128 (column-guarded).
// ---------------------------------------------------------------------------
template<bool NG>
__global__ __launch_bounds__(256, 2) void sgemm128(
    const float* __restrict__ A, const float* __restrict__ Bm,
    const float* __restrict__ bias, float* __restrict__ C,
    int M, int N, int K)
{
    __shared__ float As[2][8][132];   // padded: conflict-free transposed stores
    __shared__ float Bs[2][8][128];

    const int tid = threadIdx.x;
    const int tx = tid & 15;          // N micro index (col = tx*8)
    const int ty = tid >> 4;          // M micro index (row = ty*8)
    const int bm = blockIdx.y * 128;
    const int bn = blockIdx.x * 128;

    // A loader: 128 rows x 8 cols, float4 per thread
    const int a_row = tid >> 1;
    const int a_col = (tid & 1) << 2;
    // B loader: 8 rows x 128 cols, float4 per thread
    const int b_row = tid >> 5;
    const int b_col = (tid & 31) << 2;

    const float* Aptr = A + (size_t)(bm + a_row) * K + a_col;
    const bool  b_ok  = !NG || (bn + b_col < N);

    float acc[8][8] = {};

    const int ntiles = K >> 3;

    // preload tile 0
    float4 av = *(const float4*)(Aptr);
    float4 bv = make_float4(0.f, 0.f, 0.f, 0.f);
    if (b_ok) bv = *(const float4*)(Bm + (size_t)b_row * N + bn + b_col);
    As[0][a_col + 0][a_row] = av.x;
    As[0][a_col + 1][a_row] = av.y;
    As[0][a_col + 2][a_row] = av.z;
    As[0][a_col + 3][a_row] = av.w;
    *(float4*)&Bs[0][b_row][b_col] = bv;
    __syncthreads();

    int buf = 0;
    for (int t = 0; t < ntiles; t++) {
        const bool more = (t + 1 < ntiles);
        if (more) {
            av = *(const float4*)(Aptr + (t + 1) * 8);
            if (b_ok) bv = *(const float4*)(Bm + (size_t)((t + 1) * 8 + b_row) * N + bn + b_col);
        }

        #pragma unroll
        for (int k = 0; k < 8; k++) {
            float a_[8], b_[8];
            *(float4*)&a_[0] = *(const float4*)&As[buf][k][ty * 8];
            *(float4*)&a_[4] = *(const float4*)&As[buf][k][ty * 8 + 4];
            *(float4*)&b_[0] = *(const float4*)&Bs[buf][k][tx * 8];
            *(float4*)&b_[4] = *(const float4*)&Bs[buf][k][tx * 8 + 4];
            #pragma unroll
            for (int i = 0; i < 8; i++)
                #pragma unroll
                for (int j = 0; j < 8; j++)
                    acc[i][j] = fmaf(a_[i], b_[j], acc[i][j]);
        }

        if (more) {
            const int nb = buf ^ 1;
            As[nb][a_col + 0][a_row] = av.x;
            As[nb][a_col + 1][a_row] = av.y;
            As[nb][a_col + 2][a_row] = av.z;
            As[nb][a_col + 3][a_row] = av.w;
            *(float4*)&Bs[nb][b_row][b_col] = bv;
            __syncthreads();
            buf = nb;
        }
    }

    // bias for this thread's 8 columns
    float bias8[8];
    #pragma unroll
    for (int j = 0; j < 8; j++) {
        const int col = bn + tx * 8 + j;
        bias8[j] = (!NG || col < N) ? bias[col] : 0.f;
    }

    #pragma unroll
    for (int i = 0; i < 8; i++) {
        const int row = bm + ty * 8 + i;
        float* crow = C + (size_t)row * N + bn + tx * 8;
        if (!NG || (bn + tx * 8 + 3 < N)) {
            float4 o0 = make_float4(acc[i][0] + bias8[0], acc[i][1] + bias8[1],
                                    acc[i][2] + bias8[2], acc[i][3] + bias8[3]);
            *(float4*)crow = o0;
        }
        if (!NG || (bn + tx * 8 + 7 < N)) {
            float4 o1 = make_float4(acc[i][4] + bias8[4], acc[i][5] + bias8[5],
                                    acc[i][6] + bias8[6], acc[i][7] + bias8[7]);
            *(float4*)(crow + 4) = o1;
        }
    }
}

// ---------------------------------------------------------------------------
// Sampler: warp covers 4 heads. lane group g = lane>>3 -> head hbase+g,
// slot s = lane&7 -> channels s*4..s*4+3 (float4). Two warps per query.
// ---------------------------------------------------------------------------
__global__ __launch_bounds__(256) void sample_kernel4(const float* __restrict__ ref)
{
    const int gw   = (blockIdx.x * 256 + threadIdx.x) >> 5;
    const int lane = threadIdx.x & 31;
    const int m     = gw >> 1;
    const int hbase = (gw & 1) << 2;
    const int g = lane >> 3;
    const int s = lane & 7;
    const int h = hbase + g;
    const int b = m >> 14;   // m / NQ_

    const float rx = __ldg(&ref[2 * m + 0]);
    const float ry = __ldg(&ref[2 * m + 1]);

    const float* qp = g_qp + (size_t)m * 96;

    // softmax over this head's 4 logits (vectorized across lane groups)
    const float4 lg = *(const float4*)(qp + 64 + h * 4);
    const float mx = fmaxf(fmaxf(lg.x, lg.y), fmaxf(lg.z, lg.w));
    const float e0 = __expf(lg.x - mx), e1 = __expf(lg.y - mx);
    const float e2 = __expf(lg.z - mx), e3 = __expf(lg.w - mx);
    const float inv = 1.f / (e0 + e1 + e2 + e3);
    const float w4[4] = {e0 * inv, e1 * inv, e2 * inv, e3 * inv};

    const float4 o01 = *(const float4*)(qp + h * 8);
    const float4 o23 = *(const float4*)(qp + h * 8 + 4);
    const float offx[4] = {o01.x, o01.z, o23.x, o23.z};
    const float offy[4] = {o01.y, o01.w, o23.y, o23.w};

    const float* vb = g_vproj + (size_t)b * HW_ * C_ + h * HD_ + s * 4;

    float ax = 0.f, ay = 0.f, az = 0.f, aw = 0.f;

    #pragma unroll
    for (int p = 0; p < 4; p++) {
        const float lx = fminf(fmaxf(rx + offx[p] * (0.1f / W_), 0.f), 1.f);
        const float ly = fminf(fmaxf(ry + offy[p] * (0.1f / H_), 0.f), 1.f);
        const float ixf = lx * (float)W_ - 0.5f;
        const float iyf = ly * (float)H_ - 0.5f;
        const float x0f = floorf(ixf), y0f = floorf(iyf);
        const float wx = ixf - x0f, wy = iyf - y0f;
        const int x0 = (int)x0f, y0 = (int)y0f;

        const bool xi0 = (x0 >= 0) & (x0 < W_);
        const bool xi1 = (x0 + 1 < W_);
        const bool yi0 = (y0 >= 0) & (y0 < H_);
        const bool yi1 = (y0 + 1 < H_);

        const float wp  = w4[p];
        const float c00 = wp * (1.f - wx) * (1.f - wy);
        const float c10 = wp * wx * (1.f - wy);
        const float c01 = wp * (1.f - wx) * wy;
        const float c11 = wp * wx * wy;

        if (yi0) {
            const float* r0 = vb + (size_t)(y0 * W_) * C_;
            if (xi0) {
                const float4 v = *(const float4*)(r0 + (size_t)x0 * C_);
                ax = fmaf(c00, v.x, ax); ay = fmaf(c00, v.y, ay);
                az = fmaf(c00, v.z, az); aw = fmaf(c00, v.w, aw);
            }
            if (xi1) {
                const float4 v = *(const float4*)(r0 + (size_t)(x0 + 1) * C_);
                ax = fmaf(c10, v.x, ax); ay = fmaf(c10, v.y, ay);
                az = fmaf(c10, v.z, az); aw = fmaf(c10, v.w, aw);
            }
        }
        if (yi1) {
            const float* r1 = vb + (size_t)((y0 + 1) * W_) * C_;
            if (xi0) {
                const float4 v = *(const float4*)(r1 + (size_t)x0 * C_);
                ax = fmaf(c01, v.x, ax); ay = fmaf(c01, v.y, ay);
                az = fmaf(c01, v.z, az); aw = fmaf(c01, v.w, aw);
            }
            if (xi1) {
                const float4 v = *(const float4*)(r1 + (size_t)(x0 + 1) * C_);
                ax = fmaf(c11, v.x, ax); ay = fmaf(c11, v.y, ay);
                az = fmaf(c11, v.z, az); aw = fmaf(c11, v.w, aw);
            }
        }
    }

    *(float4*)(g_sampled + (size_t)m * C_ + h * HD_ + s * 4) = make_float4(ax, ay, az, aw);
}

// ---------------------------------------------------------------------------
extern "C" void kernel_launch(void* const* d_in, const int* in_sizes, int n_in,
                              void* d_out, int out_size)
{
    const float* query  = (const float*)d_in[0];
    const float* refp   = (const float*)d_in[1];
    const float* value  = (const float*)d_in[2];
    const float* W_off  = (const float*)d_in[3];
    const float* b_off  = (const float*)d_in[4];
    const float* W_attn = (const float*)d_in[5];
    const float* b_attn = (const float*)d_in[6];
    const float* W_v    = (const float*)d_in[7];
    const float* b_v    = (const float*)d_in[8];
    const float* W_out  = (const float*)d_in[9];
    const float* b_out  = (const float*)d_in[10];
    float* out = (float*)d_out;

    float *p_qp, *p_vp, *p_s, *p_Wqp, *p_bqp;
    cudaGetSymbolAddress((void**)&p_qp,  g_qp);
    cudaGetSymbolAddress((void**)&p_vp,  g_vproj);
    cudaGetSymbolAddress((void**)&p_s,   g_sampled);
    cudaGetSymbolAddress((void**)&p_Wqp, g_Wqp);
    cudaGetSymbolAddress((void**)&p_bqp, g_bqp);

    dim3 blk(256);

    // 0) pack offset+attn weights into one [256,96] matrix
    pack_qp<<<(256 * 96 + 255) / 256, blk>>>(W_off, b_off, W_attn, b_attn);
    // 1) fused offset+logit projection: [M,256] @ [256,96]
    sgemm128<true><<<dim3(1, M_ / 128), blk>>>(query, p_Wqp, p_bqp, p_qp, M_, 96, C_);
    // 2) value projection: [M,256] @ [256,256]
    sgemm128<false><<<dim3(C_ / 128, M_ / 128), blk>>>(value, W_v, b_v, p_vp, M_, C_, C_);
    // 3) softmax + bilinear deformable sampling
    sample_kernel4<<<(M_ * 2 * 32) / 256, blk>>>(refp);
    // 4) output projection: [M,256] @ [256,256] -> d_out
    sgemm128<false><<<dim3(C_ / 128, M_ / 128), blk>>>(p_s, W_out, b_out, out, M_, C_, C_);
}

// round 4
// speedup vs baseline: 3.2160x; 2.4481x over previous
#include <cuda_runtime.h>
#include <cstdint>

// Problem constants (fixed by the dataset)
#define B_   4
#define NQ_  16384
#define C_   256
#define NH_  8
#define NP_  4
#define H_   128
#define W_   128
#define HD_  32
#define M_   (B_ * NQ_)      // 65536 rows
#define HW_  (H_ * W_)       // 16384

// Scratch (__device__ globals: allocation-free rule)
__device__ float g_qp     [(size_t)M_ * 128];       // [M, 64 off | 32 logits | 32 pad]
__device__ float g_vproj  [(size_t)B_ * HW_ * C_];  // [B, HW, C]
__device__ float g_sampled[(size_t)M_ * C_];        // [M, C]
__device__ float g_Wqpt   [128 * 256];              // [N=128 pad, K=256] tf32
__device__ float g_bqp    [128];
__device__ float g_Wvt    [256 * 256];              // W_v^T  [N,K] tf32
__device__ float g_Wot    [256 * 256];              // W_out^T [N,K] tf32

__device__ __forceinline__ uint32_t f2tf32(float x) {
    uint32_t r;
    asm("cvt.rna.tf32.f32 %0, %1;" : "=r"(r) : "f"(x));
    return r;
}

// m16n8k8 tf32 MMA (A row-major frag, B col-major frag), fp32 accumulate
__device__ __forceinline__ void mma_t(float* d, const uint32_t* a, const uint32_t* b) {
    asm volatile(
        "mma.sync.aligned.m16n8k8.row.col.f32.tf32.tf32.f32 "
        "{%0,%1,%2,%3}, {%4,%5,%6,%7}, {%8,%9}, {%0,%1,%2,%3};"
        : "+f"(d[0]), "+f"(d[1]), "+f"(d[2]), "+f"(d[3])
        : "r"(a[0]), "r"(a[1]), "r"(a[2]), "r"(a[3]), "r"(b[0]), "r"(b[1]));
}

// ---------------------------------------------------------------------------
// Pack kernels: transpose weights to [N,K] (K contiguous), round to tf32.
// ---------------------------------------------------------------------------
__global__ void pack_qp_t(const float* __restrict__ W_off, const float* __restrict__ b_off,
                          const float* __restrict__ W_attn, const float* __restrict__ b_attn)
{
    int idx = blockIdx.x * 256 + threadIdx.x;       // [0, 128*256)
    int n = idx >> 8, k = idx & 255;
    float v = 0.f;
    if (n < 64)       v = W_off[k * 64 + n];
    else if (n < 96)  v = W_attn[k * 32 + (n - 64)];
    g_Wqpt[idx] = __uint_as_float(f2tf32(v));
    if (idx < 128)
        g_bqp[idx] = (idx < 64) ? b_off[idx] : (idx < 96 ? b_attn[idx - 64] : 0.f);
}
__global__ void pack_t256(const float* __restrict__ W, float* __restrict__ dst)
{
    int idx = blockIdx.x * 256 + threadIdx.x;       // [0, 256*256)
    int n = idx >> 8, k = idx & 255;
    dst[idx] = __uint_as_float(f2tf32(W[k * 256 + n]));
}

// ---------------------------------------------------------------------------
// tf32 mma.sync GEMM: C[bm:bm+128, bn:bn+128] = A[M,256] @ Bt[N,256]^T + bias
// 256 threads = 8 warps (2 M x 4 N), warp tile 64x32, double-buffered K=32.
// ---------------------------------------------------------------------------
#define PITCH 36   // floats; (4r+c)%32 distinct for r<8,c<8 -> conflict-free frags
static constexpr int GEMM_SMEM = 4 * 128 * PITCH * 4;   // 73728 B

__global__ __launch_bounds__(256) void tf32_gemm(
    const float* __restrict__ A, const float* __restrict__ Bt,
    const float* __restrict__ bias, float* __restrict__ C, int Ncols)
{
    extern __shared__ float sm[];
    float* AsBase = sm;                          // [2][128][PITCH]
    float* BsBase = sm + 2 * 128 * PITCH;        // [2][128][PITCH]

    const int tid  = threadIdx.x;
    const int lane = tid & 31;
    const int wid  = tid >> 5;
    const int wm = (wid & 1) * 64;      // warp M offset within tile
    const int wn = (wid >> 1) * 32;     // warp N offset within tile
    const int bm = blockIdx.y * 128;
    const int bn = blockIdx.x * 128;

    const int qr = lane >> 2;           // 0..7
    const int qc = lane & 3;            // 0..3

    // global loaders: thread covers rows lr, lr+32, lr+64, lr+96 at col group lc
    const int lr = tid >> 3;            // 0..31
    const int lc = (tid & 7) * 4;       // 0..28

    const float* Ab = A  + (size_t)(bm + lr) * 256 + lc;
    const float* Bb = Bt + (size_t)(bn + lr) * 256 + lc;

    float acc[4][4][4];
    #pragma unroll
    for (int i = 0; i < 4; i++)
        #pragma unroll
        for (int j = 0; j < 4; j++)
            #pragma unroll
            for (int q = 0; q < 4; q++) acc[i][j][q] = 0.f;

    // chunk 0 -> buffer 0
    #pragma unroll
    for (int i = 0; i < 4; i++) {
        float4 va = *(const float4*)(Ab + (size_t)i * 32 * 256);
        float4 vb = *(const float4*)(Bb + (size_t)i * 32 * 256);
        float* ad = AsBase + (lr + i * 32) * PITCH + lc;
        float* bd = BsBase + (lr + i * 32) * PITCH + lc;
        ad[0] = __uint_as_float(f2tf32(va.x)); ad[1] = __uint_as_float(f2tf32(va.y));
        ad[2] = __uint_as_float(f2tf32(va.z)); ad[3] = __uint_as_float(f2tf32(va.w));
        *(float4*)bd = vb;
    }
    __syncthreads();

    float4 pa[4], pb[4];

    #pragma unroll 1
    for (int c = 0; c < 8; c++) {
        const float* Ac = AsBase + (c & 1) * 128 * PITCH;
        const float* Bc = BsBase + (c & 1) * 128 * PITCH;

        if (c < 7) {
            const int ko = (c + 1) * 32;
            #pragma unroll
            for (int i = 0; i < 4; i++) {
                pa[i] = *(const float4*)(Ab + (size_t)i * 32 * 256 + ko);
                pb[i] = *(const float4*)(Bb + (size_t)i * 32 * 256 + ko);
            }
        }

        #pragma unroll
        for (int ks = 0; ks < 4; ks++) {
            const int kc = ks * 8;
            uint32_t af[4][4], bf[4][2];
            #pragma unroll
            for (int i = 0; i < 4; i++) {
                const float* ap = Ac + (wm + i * 16 + qr) * PITCH + kc + qc;
                af[i][0] = __float_as_uint(ap[0]);
                af[i][1] = __float_as_uint(ap[8 * PITCH]);
                af[i][2] = __float_as_uint(ap[4]);
                af[i][3] = __float_as_uint(ap[8 * PITCH + 4]);
            }
            #pragma unroll
            for (int j = 0; j < 4; j++) {
                const float* bp = Bc + (wn + j * 8 + qr) * PITCH + kc + qc;
                bf[j][0] = __float_as_uint(bp[0]);
                bf[j][1] = __float_as_uint(bp[4]);
            }
            #pragma unroll
            for (int i = 0; i < 4; i++)
                #pragma unroll
                for (int j = 0; j < 4; j++)
                    mma_t(acc[i][j], af[i], bf[j]);
        }

        if (c < 7) {
            float* An = AsBase + ((c + 1) & 1) * 128 * PITCH;
            float* Bn = BsBase + ((c + 1) & 1) * 128 * PITCH;
            #pragma unroll
            for (int i = 0; i < 4; i++) {
                float* ad = An + (lr + i * 32) * PITCH + lc;
                float* bd = Bn + (lr + i * 32) * PITCH + lc;
                ad[0] = __uint_as_float(f2tf32(pa[i].x)); ad[1] = __uint_as_float(f2tf32(pa[i].y));
                ad[2] = __uint_as_float(f2tf32(pa[i].z)); ad[3] = __uint_as_float(f2tf32(pa[i].w));
                *(float4*)bd = pb[i];
            }
            __syncthreads();
        }
    }

    // Epilogue: c0/c1 at (row, col..col+1), c2/c3 at (row+8, col..col+1)
    #pragma unroll
    for (int i = 0; i < 4; i++) {
        const int r0 = bm + wm + i * 16 + qr;
        #pragma unroll
        for (int j = 0; j < 4; j++) {
            const int col = bn + wn + j * 8 + qc * 2;
            const float b0 = __ldg(&bias[col]), b1 = __ldg(&bias[col + 1]);
            float2 v0 = make_float2(acc[i][j][0] + b0, acc[i][j][1] + b1);
            float2 v1 = make_float2(acc[i][j][2] + b0, acc[i][j][3] + b1);
            *(float2*)(C + (size_t)r0 * Ncols + col) = v0;
            *(float2*)(C + (size_t)(r0 + 8) * Ncols + col) = v1;
        }
    }
}

// ---------------------------------------------------------------------------
// Sampler: warp covers 4 heads, float4 channels. qp pitch = 128.
// ---------------------------------------------------------------------------
__global__ __launch_bounds__(256) void sample_kernel4(const float* __restrict__ ref)
{
    const int gw   = (blockIdx.x * 256 + threadIdx.x) >> 5;
    const int lane = threadIdx.x & 31;
    const int m     = gw >> 1;
    const int hbase = (gw & 1) << 2;
    const int g = lane >> 3;
    const int s = lane & 7;
    const int h = hbase + g;
    const int b = m >> 14;

    const float rx = __ldg(&ref[2 * m + 0]);
    const float ry = __ldg(&ref[2 * m + 1]);

    const float* qp = g_qp + (size_t)m * 128;

    const float4 lg = *(const float4*)(qp + 64 + h * 4);
    const float mx = fmaxf(fmaxf(lg.x, lg.y), fmaxf(lg.z, lg.w));
    const float e0 = __expf(lg.x - mx), e1 = __expf(lg.y - mx);
    const float e2 = __expf(lg.z - mx), e3 = __expf(lg.w - mx);
    const float inv = 1.f / (e0 + e1 + e2 + e3);
    const float w4[4] = {e0 * inv, e1 * inv, e2 * inv, e3 * inv};

    const float4 o01 = *(const float4*)(qp + h * 8);
    const float4 o23 = *(const float4*)(qp + h * 8 + 4);
    const float offx[4] = {o01.x, o01.z, o23.x, o23.z};
    const float offy[4] = {o01.y, o01.w, o23.y, o23.w};

    const float* vb = g_vproj + (size_t)b * HW_ * C_ + h * HD_ + s * 4;

    float ax = 0.f, ay = 0.f, az = 0.f, aw = 0.f;

    #pragma unroll
    for (int p = 0; p < 4; p++) {
        const float lx = fminf(fmaxf(rx + offx[p] * (0.1f / W_), 0.f), 1.f);
        const float ly = fminf(fmaxf(ry + offy[p] * (0.1f / H_), 0.f), 1.f);
        const float ixf = lx * (float)W_ - 0.5f;
        const float iyf = ly * (float)H_ - 0.5f;
        const float x0f = floorf(ixf), y0f = floorf(iyf);
        const float wx = ixf - x0f, wy = iyf - y0f;
        const int x0 = (int)x0f, y0 = (int)y0f;

        const bool xi0 = (x0 >= 0) & (x0 < W_);
        const bool xi1 = (x0 + 1 < W_);
        const bool yi0 = (y0 >= 0) & (y0 < H_);
        const bool yi1 = (y0 + 1 < H_);

        const float wp  = w4[p];
        const float c00 = wp * (1.f - wx) * (1.f - wy);
        const float c10 = wp * wx * (1.f - wy);
        const float c01 = wp * (1.f - wx) * wy;
        const float c11 = wp * wx * wy;

        if (yi0) {
            const float* r0 = vb + (size_t)(y0 * W_) * C_;
            if (xi0) {
                const float4 v = *(const float4*)(r0 + (size_t)x0 * C_);
                ax = fmaf(c00, v.x, ax); ay = fmaf(c00, v.y, ay);
                az = fmaf(c00, v.z, az); aw = fmaf(c00, v.w, aw);
            }
            if (xi1) {
                const float4 v = *(const float4*)(r0 + (size_t)(x0 + 1) * C_);
                ax = fmaf(c10, v.x, ax); ay = fmaf(c10, v.y, ay);
                az = fmaf(c10, v.z, az); aw = fmaf(c10, v.w, aw);
            }
        }
        if (yi1) {
            const float* r1 = vb + (size_t)((y0 + 1) * W_) * C_;
            if (xi0) {
                const float4 v = *(const float4*)(r1 + (size_t)x0 * C_);
                ax = fmaf(c01, v.x, ax); ay = fmaf(c01, v.y, ay);
                az = fmaf(c01, v.z, az); aw = fmaf(c01, v.w, aw);
            }
            if (xi1) {
                const float4 v = *(const float4*)(r1 + (size_t)(x0 + 1) * C_);
                ax = fmaf(c11, v.x, ax); ay = fmaf(c11, v.y, ay);
                az = fmaf(c11, v.z, az); aw = fmaf(c11, v.w, aw);
            }
        }
    }

    *(float4*)(g_sampled + (size_t)m * C_ + h * HD_ + s * 4) = make_float4(ax, ay, az, aw);
}

// ---------------------------------------------------------------------------
extern "C" void kernel_launch(void* const* d_in, const int* in_sizes, int n_in,
                              void* d_out, int out_size)
{
    const float* query  = (const float*)d_in[0];
    const float* refp   = (const float*)d_in[1];
    const float* value  = (const float*)d_in[2];
    const float* W_off  = (const float*)d_in[3];
    const float* b_off  = (const float*)d_in[4];
    const float* W_attn = (const float*)d_in[5];
    const float* b_attn = (const float*)d_in[6];
    const float* W_v    = (const float*)d_in[7];
    const float* b_v    = (const float*)d_in[8];
    const float* W_out  = (const float*)d_in[9];
    const float* b_out  = (const float*)d_in[10];
    float* out = (float*)d_out;

    float *p_qp, *p_vp, *p_s, *p_Wqpt, *p_bqp, *p_Wvt, *p_Wot;
    cudaGetSymbolAddress((void**)&p_qp,   g_qp);
    cudaGetSymbolAddress((void**)&p_vp,   g_vproj);
    cudaGetSymbolAddress((void**)&p_s,    g_sampled);
    cudaGetSymbolAddress((void**)&p_Wqpt, g_Wqpt);
    cudaGetSymbolAddress((void**)&p_bqp,  g_bqp);
    cudaGetSymbolAddress((void**)&p_Wvt,  g_Wvt);
    cudaGetSymbolAddress((void**)&p_Wot,  g_Wot);

    cudaFuncSetAttribute(tf32_gemm, cudaFuncAttributeMaxDynamicSharedMemorySize, GEMM_SMEM);

    // 0) pack/transpose/round weights
    pack_qp_t<<<128, 256>>>(W_off, b_off, W_attn, b_attn);
    pack_t256<<<256, 256>>>(W_v, p_Wvt);
    pack_t256<<<256, 256>>>(W_out, p_Wot);
    // 1) fused offset+logit projection: [M,256] x [256,128pad] -> g_qp (pitch 128)
    tf32_gemm<<<dim3(1, M_ / 128), 256, GEMM_SMEM>>>(query, p_Wqpt, p_bqp, p_qp, 128);
    // 2) value projection: [M,256] x [256,256]
    tf32_gemm<<<dim3(2, M_ / 128), 256, GEMM_SMEM>>>(value, p_Wvt, b_v, p_vp, 256);
    // 3) softmax + bilinear deformable sampling
    sample_kernel4<<<(M_ * 2 * 32) / 256, 256>>>(refp);
    // 4) output projection -> d_out
    tf32_gemm<<<dim3(2, M_ / 128), 256, GEMM_SMEM>>>(p_s, p_Wot, b_out, out, 256);
}